// round 7
// baseline (speedup 1.0000x reference)
#include <cuda_runtime.h>
#include <cuda_fp16.h>
#include <cstdint>

#define N_NODES 1000000
#define N_EDGES 5000000
#define N_LABEL 2000000
#define FDIM    16

#define SCAN_CHUNK 2048
#define NB ((N_NODES + SCAN_CHUNK - 1) / SCAN_CHUNK)   // 489

// Scratch (device globals — allocation is forbidden)
__device__ int      g_deg [N_NODES];
__device__ int      g_off [N_NODES];       // exclusive offsets; post-fill = off[i+1]
__device__ int      g_csr [N_EDGES];
__device__ int      g_bsum[NB];
__device__ float    g_dinv[N_NODES];
__device__ unsigned g_msg1[N_NODES * 8];   // layer-1 messages, half2-packed
__device__ unsigned g_msg2[N_NODES * 8];   // layer-2 messages, half2-packed
__device__ float    g_pA  [N_NODES];       // dot(z_i, fc_w[0:16])
__device__ float    g_pB  [N_NODES];       // dot(z_i, fc_w[16:32])

// ---------------------------------------------------------------------------
// E % 4 == 0: int4-vectorized degree count
__global__ void k_count(const int4* __restrict__ dst4) {
    int e = blockIdx.x * blockDim.x + threadIdx.x;
    if (e < N_EDGES / 4) {
        int4 d = dst4[e];
        atomicAdd(&g_deg[d.x], 1);
        atomicAdd(&g_deg[d.y], 1);
        atomicAdd(&g_deg[d.z], 1);
        atomicAdd(&g_deg[d.w], 1);
    }
}

// dinv only needs deg — runs on the side stream, unblocks mm1 early.
__global__ void k_dinv() {
    int i = blockIdx.x * blockDim.x + threadIdx.x;
    if (i < N_NODES) g_dinv[i] = rsqrtf((float)(g_deg[i] + 1));  // +1 self loop
}

// ---------------------------------------------------------------------------
// 3-phase exclusive scan of g_deg into g_off.
__global__ void k_scan1() {
    __shared__ int s[256];
    int b = blockIdx.x, t = threadIdx.x;
    int base = b * SCAN_CHUNK + t * 8;
    int v[8], sum = 0;
    #pragma unroll
    for (int q = 0; q < 8; q++) {
        int idx = base + q;
        int d = (idx < N_NODES) ? g_deg[idx] : 0;
        v[q] = sum; sum += d;
    }
    s[t] = sum; __syncthreads();
    for (int o = 1; o < 256; o <<= 1) {
        int x = (t >= o) ? s[t - o] : 0;
        __syncthreads();
        s[t] += x;
        __syncthreads();
    }
    int excl = (t > 0) ? s[t - 1] : 0;
    #pragma unroll
    for (int q = 0; q < 8; q++) {
        int idx = base + q;
        if (idx < N_NODES) g_off[idx] = v[q] + excl;
    }
    if (t == 255) g_bsum[b] = s[255];
}

__global__ void k_scan2() {
    __shared__ int s[512];
    int t = threadIdx.x;
    s[t] = (t < NB) ? g_bsum[t] : 0;
    __syncthreads();
    for (int o = 1; o < 512; o <<= 1) {
        int x = (t >= o) ? s[t - o] : 0;
        __syncthreads();
        s[t] += x;
        __syncthreads();
    }
    if (t < NB) g_bsum[t] = (t > 0) ? s[t - 1] : 0;   // exclusive
}

__global__ void k_scan3() {
    int i = blockIdx.x * blockDim.x + threadIdx.x;
    if (i < N_NODES) g_off[i] += g_bsum[i >> 11];
}

// int4-vectorized CSR fill; cursors ARE g_off (post-fill g_off[i] = off[i+1])
__global__ void k_fill(const int4* __restrict__ src4, const int4* __restrict__ dst4) {
    int e = blockIdx.x * blockDim.x + threadIdx.x;
    if (e >= N_EDGES / 4) return;
    int4 s = src4[e];
    int4 d = dst4[e];
    g_csr[atomicAdd(&g_off[d.x], 1)] = s.x;
    g_csr[atomicAdd(&g_off[d.y], 1)] = s.y;
    g_csr[atomicAdd(&g_off[d.z], 1)] = s.z;
    g_csr[atomicAdd(&g_off[d.w], 1)] = s.w;
}

// ---------------------------------------------------------------------------
// K-mm1: msg1[i] = (embed[x[i]] @ W1) * dinv[i]  (half2-packed, 32 B/node)
__global__ void k_mm1(const int* __restrict__ x,
                      const float* __restrict__ embed,
                      const float* __restrict__ W1) {
    __shared__ float Ws[FDIM][FDIM];
    if (threadIdx.x < 256) {
        int k = threadIdx.x >> 4, j = threadIdx.x & 15;
        Ws[k][j] = W1[threadIdx.x];
    }
    __syncthreads();

    int i = blockIdx.x * blockDim.x + threadIdx.x;
    if (i >= N_NODES) return;

    const float4* rp = (const float4*)(embed + (size_t)x[i] * FDIM);
    float4 r0 = rp[0], r1 = rp[1], r2 = rp[2], r3 = rp[3];
    float row[FDIM] = {r0.x,r0.y,r0.z,r0.w, r1.x,r1.y,r1.z,r1.w,
                       r2.x,r2.y,r2.z,r2.w, r3.x,r3.y,r3.z,r3.w};
    float dv = g_dinv[i];
    float out[FDIM];
    #pragma unroll
    for (int j = 0; j < FDIM; j++) {
        float acc = 0.f;
        #pragma unroll
        for (int k = 0; k < FDIM; k++) acc = fmaf(row[k], Ws[k][j], acc);
        out[j] = acc * dv;
    }
    __half2 h[8];
    #pragma unroll
    for (int q = 0; q < 8; q++) h[q] = __floats2half2_rn(out[2*q], out[2*q+1]);
    uint4* mp = (uint4*)(g_msg1 + (size_t)i * 8);
    mp[0] = make_uint4(*(unsigned*)&h[0], *(unsigned*)&h[1], *(unsigned*)&h[2], *(unsigned*)&h[3]);
    mp[1] = make_uint4(*(unsigned*)&h[4], *(unsigned*)&h[5], *(unsigned*)&h[6], *(unsigned*)&h[7]);
}

// ---------------------------------------------------------------------------
__device__ __forceinline__ void acc_h4(float4& a, uint2 m) {
    float2 f0 = __half22float2(*(__half2*)&m.x);
    float2 f1 = __half22float2(*(__half2*)&m.y);
    a.x += f0.x; a.y += f0.y; a.z += f1.x; a.w += f1.y;
}

// Gather core: 4 threads/node, uint2 loads, batches of 8 with clamped indices
// and predicated accumulate. P(deg<=8)~0.93 => typically ONE parallel wave.
__device__ __forceinline__ float4 gather_acc(const uint2* __restrict__ M,
                                             int node, int t, int o0, int o1) {
    float4 acc = make_float4(0.f, 0.f, 0.f, 0.f);
    acc_h4(acc, M[(size_t)node * 4 + t]);          // self message

    int last = o1 - 1;
    for (int j = o0; j < o1; j += 8) {
        int   idx[8];
        uint2 m[8];
        #pragma unroll
        for (int q = 0; q < 8; q++) idx[q] = g_csr[min(j + q, last)];
        #pragma unroll
        for (int q = 0; q < 8; q++) m[q] = M[(size_t)idx[q] * 4 + t];
        #pragma unroll
        for (int q = 0; q < 8; q++)
            if (j + q < o1) acc_h4(acc, m[q]);
    }
    return acc;
}

// K-gather1 fused with layer-2 matmul. Grid exact: 1e6/64 blocks — full warps.
__global__ void k_gather_mm2(const float* __restrict__ W2,
                             const float* __restrict__ b1) {
    __shared__ float Ws[FDIM][FDIM];
    __shared__ float bs[FDIM];
    if (threadIdx.x < 256) {
        int k = threadIdx.x >> 4, j = threadIdx.x & 15;
        Ws[k][j] = W2[threadIdx.x];
        if (threadIdx.x < FDIM) bs[threadIdx.x] = b1[threadIdx.x];
    }
    __syncthreads();

    int node  = blockIdx.x * 64 + (threadIdx.x >> 2);
    int t     = threadIdx.x & 3;
    int gbase = (threadIdx.x & 31) & ~3;

    int o1 = g_off[node];                 // post-fill: = original off[node+1]
    int o0 = o1 - g_deg[node];

    float4 acc = gather_acc((const uint2*)g_msg1, node, t, o0, o1);

    float dv = g_dinv[node];
    float h[4];
    h[0] = fmaxf(fmaf(dv, acc.x, bs[4*t + 0]), 0.f);
    h[1] = fmaxf(fmaf(dv, acc.y, bs[4*t + 1]), 0.f);
    h[2] = fmaxf(fmaf(dv, acc.z, bs[4*t + 2]), 0.f);
    h[3] = fmaxf(fmaf(dv, acc.w, bs[4*t + 3]), 0.f);

    float o[4] = {0.f, 0.f, 0.f, 0.f};
    #pragma unroll
    for (int k = 0; k < FDIM; k++) {
        float hk = __shfl_sync(0xFFFFFFFFu, h[k & 3], gbase + (k >> 2));
        o[0] = fmaf(hk, Ws[k][4*t + 0], o[0]);
        o[1] = fmaf(hk, Ws[k][4*t + 1], o[1]);
        o[2] = fmaf(hk, Ws[k][4*t + 2], o[2]);
        o[3] = fmaf(hk, Ws[k][4*t + 3], o[3]);
    }
    __half2 p0 = __floats2half2_rn(o[0] * dv, o[1] * dv);
    __half2 p1 = __floats2half2_rn(o[2] * dv, o[3] * dv);
    ((uint2*)g_msg2)[(size_t)node * 4 + t] =
        make_uint2(*(unsigned*)&p0, *(unsigned*)&p1);
}

// K-gather2 fused with final FC partials:
//   z = dinv*(msg2[i] + Σ msg2[s]) + b2
//   pA[i] = dot(z, fc_w[0:16]);  pB[i] = dot(z, fc_w[16:32])
__global__ void k_gather_z(const float* __restrict__ b2,
                           const float* __restrict__ fc_w) {
    __shared__ float bs[FDIM];
    __shared__ float fw[32];
    if (threadIdx.x < FDIM) bs[threadIdx.x] = b2[threadIdx.x];
    if (threadIdx.x < 32)   fw[threadIdx.x] = fc_w[threadIdx.x];
    __syncthreads();

    int node = blockIdx.x * 64 + (threadIdx.x >> 2);
    int t    = threadIdx.x & 3;

    int o1 = g_off[node];
    int o0 = o1 - g_deg[node];

    float4 acc = gather_acc((const uint2*)g_msg2, node, t, o0, o1);

    float dv = g_dinv[node];
    float z0 = fmaf(dv, acc.x, bs[4*t + 0]);
    float z1 = fmaf(dv, acc.y, bs[4*t + 1]);
    float z2 = fmaf(dv, acc.z, bs[4*t + 2]);
    float z3 = fmaf(dv, acc.w, bs[4*t + 3]);

    float pa = z0 * fw[4*t] + z1 * fw[4*t+1] + z2 * fw[4*t+2] + z3 * fw[4*t+3];
    float pb = z0 * fw[16+4*t] + z1 * fw[16+4*t+1]
             + z2 * fw[16+4*t+2] + z3 * fw[16+4*t+3];

    pa += __shfl_xor_sync(0xFFFFFFFFu, pa, 1);
    pa += __shfl_xor_sync(0xFFFFFFFFu, pa, 2);
    pb += __shfl_xor_sync(0xFFFFFFFFu, pb, 1);
    pb += __shfl_xor_sync(0xFFFFFFFFu, pb, 2);

    if (t == 0) {
        g_pA[node] = pa;
        g_pB[node] = pb;
    }
}

// ---------------------------------------------------------------------------
// K-predict: out[e] = pA[la[e]] + pB[lb[e]] + fc_b
__global__ void k_predict(const int* __restrict__ la,
                          const int* __restrict__ lb,
                          const float* __restrict__ fc_b,
                          float* __restrict__ out) {
    int e = blockIdx.x * blockDim.x + threadIdx.x;
    if (e >= N_LABEL) return;
    float fb = __ldg(fc_b);
    out[e] = g_pA[la[e]] + g_pB[lb[e]] + fb;
}

// ---------------------------------------------------------------------------
extern "C" void kernel_launch(void* const* d_in, const int* in_sizes, int n_in,
                              void* d_out, int out_size) {
    const int*   x     = (const int*)  d_in[0];
    const int*   ei    = (const int*)  d_in[1];
    const int*   eli   = (const int*)  d_in[2];
    const float* embed = (const float*)d_in[3];
    const float* W1    = (const float*)d_in[4];
    const float* b1    = (const float*)d_in[5];
    const float* W2    = (const float*)d_in[6];
    const float* b2    = (const float*)d_in[7];
    const float* fc_w  = (const float*)d_in[8];
    const float* fc_b  = (const float*)d_in[9];
    float*       out   = (float*)d_out;

    const int4* e_src4 = (const int4*)ei;
    const int4* e_dst4 = (const int4*)(ei + N_EDGES);
    const int*  l_a    = eli;
    const int*  l_b    = eli + N_LABEL;

    const int TB = 256;
    int gN  = (N_NODES + TB - 1) / TB;
    int gE4 = (N_EDGES / 4 + TB - 1) / TB;
    int gL  = (N_LABEL + TB - 1) / TB;
    int gG  = N_NODES / 64;              // exact: 15625 blocks, 4 thr/node

    static cudaStream_t s2 = nullptr;
    static cudaEvent_t  e1 = nullptr, e2 = nullptr;
    static void* degPtr = nullptr;
    if (!e1) {
        if (cudaStreamCreateWithFlags(&s2, cudaStreamNonBlocking) != cudaSuccess) s2 = nullptr;
        cudaEventCreateWithFlags(&e1, cudaEventDisableTiming);
        cudaEventCreateWithFlags(&e2, cudaEventDisableTiming);
        cudaGetSymbolAddress(&degPtr, g_deg);
    }

    cudaMemsetAsync(degPtr, 0, N_NODES * sizeof(int), 0);
    k_count<<<gE4, TB>>>(e_dst4);

    if (s2) {
        cudaEventRecord(e1, 0);
        cudaStreamWaitEvent(s2, e1, 0);
        k_dinv<<<gN, TB, 0, s2>>>();
        k_mm1 <<<gN, TB, 0, s2>>>(x, embed, W1);
        cudaEventRecord(e2, s2);
        k_scan1<<<NB, 256>>>();
        k_scan2<<<1, 512>>>();
        k_scan3<<<gN, TB>>>();
        k_fill <<<gE4, TB>>>(e_src4, e_dst4);
        cudaStreamWaitEvent(0, e2, 0);
    } else {
        k_dinv <<<gN, TB>>>();
        k_scan1<<<NB, 256>>>();
        k_scan2<<<1, 512>>>();
        k_scan3<<<gN, TB>>>();
        k_fill <<<gE4, TB>>>(e_src4, e_dst4);
        k_mm1  <<<gN, TB>>>(x, embed, W1);
    }

    k_gather_mm2<<<gG, TB>>>(W2, b1);
    k_gather_z  <<<gG, TB>>>(b2, fc_w);
    k_predict   <<<gL, TB>>>(l_a, l_b, fc_b, out);
}